// round 10
// baseline (speedup 1.0000x reference)
#include <cuda_runtime.h>
#include <cstdint>
#include <cstddef>
#include <math.h>

#define BATCH 64
#define SEQ   197
#define NHEAD 12
#define HDIM  64
#define HID   768
#define NTOK  (BATCH*SEQ)   // 12608

typedef unsigned long long ull;

// ---------------- scratch (__device__ globals: no allocation allowed) ----------
// Buffers hold DEQUANTIZED values computed with XLA's div->mul-rewritten ops.
__device__ float g_XQ[(size_t)NTOK*HID];
__device__ float g_WQ[(size_t)HID*HID];
__device__ float g_WK[(size_t)HID*HID];
__device__ float g_WV[(size_t)HID*HID];
__device__ float g_WO[(size_t)HID*HID];
__device__ float g_Q [(size_t)NTOK*HID];
__device__ float g_K [(size_t)NTOK*HID];
__device__ float g_V [(size_t)NTOK*HID];
__device__ float g_AQ[(size_t)NTOK*HID];   // dequantized attention output

// ---------------- f32x2 helpers (per-lane identical to scalar rn ops) ----------
__device__ __forceinline__ ull pk2(float a, float b) {
    ull r; asm("mov.b64 %0, {%1, %2};" : "=l"(r) : "f"(a), "f"(b)); return r;
}
__device__ __forceinline__ float2 upk2(ull v) {
    float2 r; asm("mov.b64 {%0, %1}, %2;" : "=f"(r.x), "=f"(r.y) : "l"(v)); return r;
}
__device__ __forceinline__ void fma2(ull &d, ull a, ull b) {
    asm("fma.rn.f32x2 %0, %1, %2, %0;" : "+l"(d) : "l"(a), "l"(b));
}

// ---------------- quantize-dequantize, XLA div->mul replica --------------------
// XLA rewrites x/const -> x * (1/const) with the reciprocal rounded to f32.
//   t   = clip(x * invKa, -1, 1)
//   r   = round_half_even(t * 127)
//   deq = (r * (1/127f)) * Kw          (both multiplies, rn)
#define INV127 (1.0f/127.0f)

__device__ __forceinline__ float qdq_m(float x, float invKa, float Ka) {
    float t = fminf(fmaxf(__fmul_rn(x, invKa), -1.0f), 1.0f);
    float r = rintf(__fmul_rn(t, 127.0f));
    return __fmul_rn(__fmul_rn(r, INV127), Ka);
}

__global__ void quant4_kernel(const float4* __restrict__ in, float4* __restrict__ out,
                              int n4, float invKa, float Ka) {
    int i = blockIdx.x * blockDim.x + threadIdx.x;
    int stride = gridDim.x * blockDim.x;
    for (; i < n4; i += stride) {
        float4 v = in[i];
        v.x = qdq_m(v.x, invKa, Ka);
        v.y = qdq_m(v.y, invKa, Ka);
        v.z = qdq_m(v.z, invKa, Ka);
        v.w = qdq_m(v.w, invKa, Ka);
        out[i] = v;
    }
}

// ---------------- NT GEMM: C[T,768] = A @ W^T + bias ---------------------------
// Strictly serial ascending-k FFMA chain per output element.
__global__ __launch_bounds__(256) void gemm_nt_kernel(
    const float* __restrict__ A, const float* __restrict__ W,
    const float* __restrict__ bias, float* __restrict__ C)
{
    __shared__ __align__(16) float As[16][64 + 4];
    __shared__ __align__(16) float Bs[16][128 + 4];

    const int tid = threadIdx.x;
    const int tx = tid & 15;      // n-group
    const int ty = tid >> 4;      // m-group
    const int m0 = blockIdx.x * 64;
    const int n0 = blockIdx.y * 128;

    const int lr = tid >> 2;           // 0..63
    const int lk = (tid & 3) * 4;      // 0,4,8,12

    const float* Ag  = A + (size_t)(m0 + lr) * HID + lk;
    const float* Wg0 = W + (size_t)(n0 + lr) * HID + lk;
    const float* Wg1 = Wg0 + (size_t)64 * HID;

    float4 pa  = *(const float4*)Ag;
    float4 pb0 = *(const float4*)Wg0;
    float4 pb1 = *(const float4*)Wg1;

    ull acc[4][4];
    #pragma unroll
    for (int i = 0; i < 4; i++)
        #pragma unroll
        for (int j = 0; j < 4; j++) acc[i][j] = 0ull;

    #pragma unroll 1
    for (int kt = 0; kt < 48; kt++) {
        __syncthreads();
        As[lk+0][lr] = pa.x;  As[lk+1][lr] = pa.y;
        As[lk+2][lr] = pa.z;  As[lk+3][lr] = pa.w;
        Bs[lk+0][lr] = pb0.x; Bs[lk+1][lr] = pb0.y;
        Bs[lk+2][lr] = pb0.z; Bs[lk+3][lr] = pb0.w;
        Bs[lk+0][lr+64] = pb1.x; Bs[lk+1][lr+64] = pb1.y;
        Bs[lk+2][lr+64] = pb1.z; Bs[lk+3][lr+64] = pb1.w;
        __syncthreads();

        if (kt < 47) {
            pa  = *(const float4*)(Ag  + (kt+1)*16);
            pb0 = *(const float4*)(Wg0 + (kt+1)*16);
            pb1 = *(const float4*)(Wg1 + (kt+1)*16);
        }

        #pragma unroll
        for (int k = 0; k < 16; k++) {      // ascending k
            float4 a4 = *(const float4*)&As[k][ty*4];
            ull ad0 = pk2(a4.x, a4.x);
            ull ad1 = pk2(a4.y, a4.y);
            ull ad2 = pk2(a4.z, a4.z);
            ull ad3 = pk2(a4.w, a4.w);
            ull b[4];
            #pragma unroll
            for (int j = 0; j < 4; j++)
                b[j] = *(const ull*)&Bs[k][32*j + 2*tx];
            #pragma unroll
            for (int j = 0; j < 4; j++) {
                fma2(acc[0][j], ad0, b[j]);
                fma2(acc[1][j], ad1, b[j]);
                fma2(acc[2][j], ad2, b[j]);
                fma2(acc[3][j], ad3, b[j]);
            }
        }
    }

    #pragma unroll
    for (int i = 0; i < 4; i++) {
        int row = m0 + ty*4 + i;
        #pragma unroll
        for (int j = 0; j < 4; j++) {
            int col = n0 + 32*j + 2*tx;
            float2 r = upk2(acc[i][j]);
            float2 o;
            o.x = __fadd_rn(r.x, bias[col]);
            o.y = __fadd_rn(r.y, bias[col+1]);
            *(float2*)&C[(size_t)row * HID + col] = o;
        }
    }
}

// ---------------- attention: one block per (b,h) --------------------------------
// scores: serial ascending-d FMA dot * 0.125 (exact scale)
// max: exact; u = expf(s-m) (libdevice __nv_expf = XLA exp)
// l: XLA GPU warp row-reduction order: 32 strided partials + tree 16..1
// p = u/l (div.rn); PV: serial ascending-k FMA; AO dequant via mul-rewrite ops.
__global__ __launch_bounds__(256) void attn_kernel(
    const float* __restrict__ Q, const float* __restrict__ K,
    const float* __restrict__ V, float* __restrict__ OQ)
{
    extern __shared__ __align__(16) float sm[];
    float* Ks = sm;                   // [197][64]
    float* Vs = sm + SEQ * HDIM;      // [197][64]

    const int bh = blockIdx.x;
    const int b  = bh / NHEAD;
    const int h  = bh - b * NHEAD;
    const size_t base = (size_t)b * SEQ * HID + (size_t)h * HDIM;

    const float4* Kg = (const float4*)(K + base);
    const float4* Vg = (const float4*)(V + base);
    float4* Ks4 = (float4*)Ks;
    float4* Vs4 = (float4*)Vs;
    for (int i = threadIdx.x; i < SEQ * (HDIM/4); i += 256) {
        int r = i >> 4, c = i & 15;
        size_t g = (size_t)r * (HID/4) + c;
        Ks4[i] = Kg[g];
        Vs4[i] = Vg[g];
    }
    __syncthreads();

    const int q = threadIdx.x;
    if (q >= SEQ) return;

    // Q row in registers
    float qr[HDIM];
    {
        const float4* Qp = (const float4*)(Q + base + (size_t)q * HID);
        #pragma unroll
        for (int i = 0; i < 16; i++) {
            float4 t = Qp[i];
            qr[4*i+0] = t.x; qr[4*i+1] = t.y; qr[4*i+2] = t.z; qr[4*i+3] = t.w;
        }
    }

    float sl[SEQ];
    float m = -3.402823466e+38f;

    // scores + max
    for (int k = 0; k < SEQ; k++) {
        const float* kr = Ks + k * HDIM;
        float a = 0.0f;
        #pragma unroll
        for (int d = 0; d < HDIM; d++)
            a = fmaf(qr[d], kr[d], a);
        float sv = __fmul_rn(a, 0.125f);   // exact (power of two)
        sl[k] = sv;
        m = fmaxf(m, sv);
    }

    // u = exp(s - m)
    for (int k = 0; k < SEQ; k++)
        sl[k] = expf(__fadd_rn(sl[k], -m));

    // l: warp-strided partials + tree (XLA GPU row-reduction order)
    float part[32];
    #pragma unroll
    for (int j = 0; j < 32; j++) part[j] = 0.0f;
    for (int k = 0; k < SEQ; k++)
        part[k & 31] = __fadd_rn(part[k & 31], sl[k]);
    #pragma unroll
    for (int off = 16; off >= 1; off >>= 1)
        #pragma unroll
        for (int j = 0; j < 16; j++)
            if (j < off) part[j] = __fadd_rn(part[j], part[j + off]);
    const float l = part[0];

    // p = u / l
    for (int k = 0; k < SEQ; k++)
        sl[k] = __fdiv_rn(sl[k], l);

    // PV: serial ascending-k FMA (lanes = independent d columns)
    ull acc[32];
    #pragma unroll
    for (int i = 0; i < 32; i++) acc[i] = 0ull;

    const ulonglong2* V2 = (const ulonglong2*)Vs;
    for (int k = 0; k < SEQ; k++) {
        ull pd = pk2(sl[k], sl[k]);
        const ulonglong2* vr = V2 + (size_t)k * 16;
        #pragma unroll
        for (int i = 0; i < 16; i++) {
            ulonglong2 t = vr[i];
            fma2(acc[2*i],   pd, t.x);
            fma2(acc[2*i+1], pd, t.y);
        }
    }

    // AO quantize-dequantize (Ka=4) with XLA mul-rewrite ops (x*0.25 exact)
    float* dst = OQ + base + (size_t)q * HID;
    #pragma unroll
    for (int i = 0; i < 32; i++) {
        float2 v = upk2(acc[i]);
        dst[2*i]   = qdq_m(v.x, 0.25f, 4.0f);
        dst[2*i+1] = qdq_m(v.y, 0.25f, 4.0f);
    }
}

// ---------------- launch ------------------------------------------------------
extern "C" void kernel_launch(void* const* d_in, const int* in_sizes, int n_in,
                              void* d_out, int out_size) {
    const float* x  = (const float*)d_in[0];
    const float* wq = (const float*)d_in[1];
    const float* bq = (const float*)d_in[2];
    const float* wk = (const float*)d_in[3];
    const float* bk = (const float*)d_in[4];
    const float* wv = (const float*)d_in[5];
    const float* bv = (const float*)d_in[6];
    const float* wo = (const float*)d_in[7];
    const float* bo = (const float*)d_in[8];
    float* out = (float*)d_out;

    float *XQ, *WQ, *WK, *WV, *WO, *Qb, *Kb, *Vb, *AQ;
    cudaGetSymbolAddress((void**)&XQ, g_XQ);
    cudaGetSymbolAddress((void**)&WQ, g_WQ);
    cudaGetSymbolAddress((void**)&WK, g_WK);
    cudaGetSymbolAddress((void**)&WV, g_WV);
    cudaGetSymbolAddress((void**)&WO, g_WO);
    cudaGetSymbolAddress((void**)&Qb, g_Q);
    cudaGetSymbolAddress((void**)&Kb, g_K);
    cudaGetSymbolAddress((void**)&Vb, g_V);
    cudaGetSymbolAddress((void**)&AQ, g_AQ);

    const int nX4 = NTOK * HID / 4;
    const int nW4 = HID * HID / 4;

    // reciprocal constants as XLA's div->mul rewrite produces them:
    // 1/4.0f = 0.25f (exact); 1/0.1f rounds to exactly 10.0f.
    const float invKaI = 0.25f;
    const float invKwW = 10.0f;

    // 1) quantize-dequantize activations and weights (XLA-rewritten f32 ops)
    quant4_kernel<<<(nX4 + 255)/256, 256>>>((const float4*)x,  (float4*)XQ, nX4, invKaI, 4.0f);
    quant4_kernel<<<(nW4 + 255)/256, 256>>>((const float4*)wq, (float4*)WQ, nW4, invKwW, 0.1f);
    quant4_kernel<<<(nW4 + 255)/256, 256>>>((const float4*)wk, (float4*)WK, nW4, invKwW, 0.1f);
    quant4_kernel<<<(nW4 + 255)/256, 256>>>((const float4*)wv, (float4*)WV, nW4, invKwW, 0.1f);
    quant4_kernel<<<(nW4 + 255)/256, 256>>>((const float4*)wo, (float4*)WO, nW4, invKwW, 0.1f);

    // 2) Q/K/V projections (serial-k FMA)
    dim3 ggrid(NTOK/64, HID/128);   // (197, 6)
    gemm_nt_kernel<<<ggrid, 256>>>(XQ, WQ, bq, Qb);
    gemm_nt_kernel<<<ggrid, 256>>>(XQ, WK, bk, Kb);
    gemm_nt_kernel<<<ggrid, 256>>>(XQ, WV, bv, Vb);

    // 3) attention; emits dequantized AO
    const int attn_smem = 2 * SEQ * HDIM * (int)sizeof(float);
    cudaFuncSetAttribute(attn_kernel, cudaFuncAttributeMaxDynamicSharedMemorySize, attn_smem);
    attn_kernel<<<BATCH * NHEAD, 256, attn_smem>>>(Qb, Kb, Vb, AQ);

    // 4) O-projection on dequantized AO
    gemm_nt_kernel<<<ggrid, 256>>>(AQ, WO, bo, out);
}